// round 1
// baseline (speedup 1.0000x reference)
#include <cuda_runtime.h>
#include <cuda_bf16.h>
#include <math.h>

// Problem constants (shapes are fixed for this dataset)
#define MAXN 50000
#define MAXE 800000
#define MAXG 512
#define HID  256

// Scratch (static __device__ arrays: allocation-free per harness rules)
__device__ float g_bufA[(size_t)MAXN * HID];   // aggregation output
__device__ float g_bufB[(size_t)MAXN * HID];   // post-GEMM hidden
__device__ float g_dis[MAXN];                  // deg^{-1/2}
__device__ int   g_counts[MAXN];
__device__ int   g_offs[MAXN + 1];
__device__ int   g_wptr[MAXN];
__device__ int   g_csr[MAXE];
__device__ float g_sums[MAXG * HID];
__device__ int   g_gcnt[MAXG];

// ---------------------------------------------------------------------------
// 0. zero-init scratch that must start at 0 each call
__global__ void init_kernel(int n_nodes, int n_graphs) {
    int i = blockIdx.x * blockDim.x + threadIdx.x;
    int total = n_nodes + n_graphs + n_graphs * HID;
    for (; i < total; i += gridDim.x * blockDim.x) {
        if (i < n_nodes) g_counts[i] = 0;
        else if (i < n_nodes + n_graphs) g_gcnt[i - n_nodes] = 0;
        else g_sums[i - n_nodes - n_graphs] = 0.0f;
    }
}

// 1. in-degree counts (dst side of edges; self-loops handled as +1 later)
__global__ void count_kernel(const int* __restrict__ ei, int E) {
    int e = blockIdx.x * blockDim.x + threadIdx.x;
    if (e < E) atomicAdd(&g_counts[ei[E + e]], 1);
}

// 2. single-block exclusive scan of counts -> offsets, also deg_inv_sqrt
__global__ void scan_kernel(int n) {
    __shared__ int smem[1024];
    __shared__ int carry;
    if (threadIdx.x == 0) carry = 0;
    __syncthreads();
    for (int base = 0; base < n; base += 1024) {
        int i = base + (int)threadIdx.x;
        int v = (i < n) ? g_counts[i] : 0;
        smem[threadIdx.x] = v;
        __syncthreads();
        #pragma unroll
        for (int d = 1; d < 1024; d <<= 1) {
            int t = (threadIdx.x >= (unsigned)d) ? smem[threadIdx.x - d] : 0;
            __syncthreads();
            smem[threadIdx.x] += t;
            __syncthreads();
        }
        int incl = smem[threadIdx.x];
        if (i < n) {
            int excl = carry + incl - v;
            g_offs[i] = excl;
            g_wptr[i] = excl;
            g_dis[i]  = rsqrtf(1.0f + (float)v);   // deg = 1 (self loop) + count
        }
        __syncthreads();
        if (threadIdx.x == 1023) carry += smem[1023];
        __syncthreads();
    }
    if (threadIdx.x == 0) g_offs[n] = carry;
}

// 3. fill CSR (dst-major adjacency of incoming sources)
__global__ void fill_kernel(const int* __restrict__ ei, int E) {
    int e = blockIdx.x * blockDim.x + threadIdx.x;
    if (e < E) {
        int s = ei[e];
        int d = ei[E + e];
        int p = atomicAdd(&g_wptr[d], 1);
        g_csr[p] = s;
    }
}

// ---------------------------------------------------------------------------
// 4. normalized aggregation: out[i] = dis[i] * (dis[i]*h[i] + sum_e dis[src]*h[src])
template <int F>
__global__ void agg_kernel(const float* __restrict__ h, float* __restrict__ out) {
    int node = blockIdx.x;
    int f = threadIdx.x;           // blockDim == F
    float di = g_dis[node];
    float acc = di * h[(size_t)node * F + f];
    int e0 = g_offs[node], e1 = g_offs[node + 1];
    __shared__ int   s_src[64];
    __shared__ float s_w[64];
    for (int base = e0; base < e1; base += 64) {
        int n = min(64, e1 - base);
        if (f < n) {
            int s = g_csr[base + f];
            s_src[f] = s;
            s_w[f]   = g_dis[s];
        }
        __syncthreads();
        for (int j = 0; j < n; j++)
            acc += s_w[j] * h[(size_t)s_src[j] * F + f];
        __syncthreads();
    }
    out[(size_t)node * F + f] = di * acc;
}

// ---------------------------------------------------------------------------
// 5. SGEMM: C[M,256] = relu(A[M,K] @ W[K,256] + bias), BM=128 BN=128 BK=8, 256 thr
__global__ void __launch_bounds__(256)
gemm_bias_relu(const float* __restrict__ A, const float* __restrict__ W,
               const float* __restrict__ bias, float* __restrict__ C,
               int M, int K) {
    const int BM = 128, BN = 128, BK = 8;
    __shared__ float As[BK * BM];
    __shared__ float Bs[BK * BN];
    int tid = threadIdx.x;
    int bm = blockIdx.y, bn = blockIdx.x;

    int rowA = tid >> 1;          // 0..127
    int colA = (tid & 1) * 4;     // 0 or 4
    int rowB = tid >> 5;          // 0..7
    int colB = (tid & 31) * 4;    // 0..124
    int tr = tid >> 4;            // 0..15
    int tc = tid & 15;            // 0..15

    float acc[8][8];
    #pragma unroll
    for (int i = 0; i < 8; i++)
        #pragma unroll
        for (int j = 0; j < 8; j++) acc[i][j] = 0.0f;

    const float* Aptr = A + (size_t)(bm * BM) * K;
    int globalRowA = bm * BM + rowA;
    bool rowOK = (globalRowA < M);

    for (int k0 = 0; k0 < K; k0 += BK) {
        float4 av = make_float4(0.f, 0.f, 0.f, 0.f);
        if (rowOK) av = *(const float4*)(Aptr + (size_t)rowA * K + k0 + colA);
        As[(colA + 0) * BM + rowA] = av.x;
        As[(colA + 1) * BM + rowA] = av.y;
        As[(colA + 2) * BM + rowA] = av.z;
        As[(colA + 3) * BM + rowA] = av.w;
        float4 bv = *(const float4*)(W + (size_t)(k0 + rowB) * 256 + bn * BN + colB);
        *(float4*)(Bs + rowB * BN + colB) = bv;
        __syncthreads();
        #pragma unroll
        for (int k = 0; k < BK; k++) {
            float rm[8], rn[8];
            *(float4*)(rm)     = *(const float4*)(As + k * BM + tr * 8);
            *(float4*)(rm + 4) = *(const float4*)(As + k * BM + tr * 8 + 4);
            *(float4*)(rn)     = *(const float4*)(Bs + k * BN + tc * 8);
            *(float4*)(rn + 4) = *(const float4*)(Bs + k * BN + tc * 8 + 4);
            #pragma unroll
            for (int i = 0; i < 8; i++)
                #pragma unroll
                for (int j = 0; j < 8; j++)
                    acc[i][j] += rm[i] * rn[j];
        }
        __syncthreads();
    }

    int col0 = bn * BN + tc * 8;
    float bz[8];
    #pragma unroll
    for (int j = 0; j < 8; j++) bz[j] = bias[col0 + j];
    #pragma unroll
    for (int i = 0; i < 8; i++) {
        int r = bm * BM + tr * 8 + i;
        if (r < M) {
            float4 o0, o1;
            o0.x = fmaxf(acc[i][0] + bz[0], 0.f);
            o0.y = fmaxf(acc[i][1] + bz[1], 0.f);
            o0.z = fmaxf(acc[i][2] + bz[2], 0.f);
            o0.w = fmaxf(acc[i][3] + bz[3], 0.f);
            o1.x = fmaxf(acc[i][4] + bz[4], 0.f);
            o1.y = fmaxf(acc[i][5] + bz[5], 0.f);
            o1.z = fmaxf(acc[i][6] + bz[6], 0.f);
            o1.w = fmaxf(acc[i][7] + bz[7], 0.f);
            *(float4*)(C + (size_t)r * 256 + col0)     = o0;
            *(float4*)(C + (size_t)r * 256 + col0 + 4) = o1;
        }
    }
}

// ---------------------------------------------------------------------------
// 6. mean-pool accumulation (atomics into per-graph sums)
__global__ void pool_kernel(const float* __restrict__ h, const int* __restrict__ batch) {
    int node = blockIdx.x;
    int g = batch[node];
    if (threadIdx.x == 0) atomicAdd(&g_gcnt[g], 1);
    atomicAdd(&g_sums[g * HID + threadIdx.x], h[(size_t)node * HID + threadIdx.x]);
}

// 7. head: mean, concat [molwt, nrings], fc1(relu), fc2 -> out[G,16]
__global__ void head_kernel(const float* __restrict__ molwt, const float* __restrict__ nrings,
                            const float* __restrict__ fcW1, const float* __restrict__ fcb1,
                            const float* __restrict__ fcW2, const float* __restrict__ fcb2,
                            float* __restrict__ out) {
    int g = blockIdx.x;
    __shared__ float hg[258];
    __shared__ float h1[196];
    int t = threadIdx.x;   // 256
    float c = fmaxf((float)g_gcnt[g], 1.0f);
    hg[t] = g_sums[g * HID + t] / c;
    if (t == 0) { hg[256] = molwt[g]; hg[257] = nrings[g]; }
    __syncthreads();
    if (t < 196) {
        float a = fcb1[t];
        #pragma unroll 4
        for (int k = 0; k < 258; k++) a += hg[k] * fcW1[k * 196 + t];
        h1[t] = fmaxf(a, 0.0f);
    }
    __syncthreads();
    if (t < 16) {
        float a = fcb2[t];
        #pragma unroll 4
        for (int k = 0; k < 196; k++) a += h1[k] * fcW2[k * 16 + t];
        out[g * 16 + t] = a;
    }
}

// ---------------------------------------------------------------------------
extern "C" void kernel_launch(void* const* d_in, const int* in_sizes, int n_in,
                              void* d_out, int out_size) {
    const float* x      = (const float*)d_in[0];
    const int*   ei     = (const int*)  d_in[1];
    const int*   batch  = (const int*)  d_in[2];
    const float* molwt  = (const float*)d_in[3];
    const float* nrings = (const float*)d_in[4];
    const float* W1 = (const float*)d_in[5];
    const float* b1 = (const float*)d_in[6];
    const float* W2 = (const float*)d_in[7];
    const float* b2 = (const float*)d_in[8];
    const float* W3 = (const float*)d_in[9];
    const float* b3 = (const float*)d_in[10];
    const float* fcW1 = (const float*)d_in[11];
    const float* fcb1 = (const float*)d_in[12];
    const float* fcW2 = (const float*)d_in[13];
    const float* fcb2 = (const float*)d_in[14];

    const int N = in_sizes[2];          // 50000 nodes
    const int E = in_sizes[1] / 2;      // 800000 edges
    const int G = in_sizes[3];          // 512 graphs
    const int F_IN = in_sizes[0] / N;   // 128

    float *bufA, *bufB;
    cudaGetSymbolAddress((void**)&bufA, g_bufA);
    cudaGetSymbolAddress((void**)&bufB, g_bufB);

    // graph structure (rebuilt every call: deterministic, input-only dependent)
    init_kernel<<<256, 256>>>(N, G);
    count_kernel<<<(E + 255) / 256, 256>>>(ei, E);
    scan_kernel<<<1, 1024>>>(N);
    fill_kernel<<<(E + 255) / 256, 256>>>(ei, E);

    dim3 ggrid(2, (N + 127) / 128);

    // layer 1: agg(x) [N,128] -> gemm W1 -> h [N,256]
    agg_kernel<128><<<N, 128>>>(x, bufA);
    gemm_bias_relu<<<ggrid, 256>>>(bufA, W1, b1, bufB, N, F_IN);
    // layer 2
    agg_kernel<256><<<N, 256>>>(bufB, bufA);
    gemm_bias_relu<<<ggrid, 256>>>(bufA, W2, b2, bufB, N, HID);
    // layer 3
    agg_kernel<256><<<N, 256>>>(bufB, bufA);
    gemm_bias_relu<<<ggrid, 256>>>(bufA, W3, b3, bufB, N, HID);

    // pooling + head
    pool_kernel<<<N, 256>>>(bufB, batch);
    head_kernel<<<G, 256>>>(molwt, nrings, fcW1, fcb1, fcW2, fcb2, (float*)d_out);
}

// round 3
// speedup vs baseline: 1.3133x; 1.3133x over previous
#include <cuda_runtime.h>
#include <cuda_bf16.h>
#include <cstdint>
#include <math.h>

// Problem constants (fixed for this dataset)
#define MAXN 50000
#define MAXE 800000
#define MAXG 512
#define HID  256

// ---------------------------------------------------------------------------
// Scratch (__device__ globals: allocation-free per harness rules)
__device__ __nv_bfloat16 g_Ah[(size_t)MAXN * HID];   // agg output, bf16 hi
__device__ __nv_bfloat16 g_Al[(size_t)MAXN * HID];   // agg output, bf16 lo
__device__ float g_bufB[(size_t)MAXN * HID];         // post-GEMM hidden (fp32)
__device__ float g_dis[MAXN];
__device__ int   g_counts[MAXN];
__device__ int   g_offs[MAXN + 1];
__device__ int   g_wptr[MAXN];
__device__ int   g_csr[MAXE];
__device__ float g_sums[MAXG * HID];
__device__ int   g_gcnt[MAXG];
// split+transposed weights: [N=256 rows][K cols], K-major bf16
__device__ __nv_bfloat16 g_Wh1[256 * 128], g_Wl1[256 * 128];
__device__ __nv_bfloat16 g_Wh2[256 * 256], g_Wl2[256 * 256];
__device__ __nv_bfloat16 g_Wh3[256 * 256], g_Wl3[256 * 256];

// ---------------------------------------------------------------------------
// base-ISA tensor helpers (mma.sync / ldmatrix / cp.async — no sm_103a features)
__device__ __forceinline__ void ldsm_x4(uint32_t& r0, uint32_t& r1, uint32_t& r2, uint32_t& r3,
                                        uint32_t addr) {
    asm volatile("ldmatrix.sync.aligned.m8n8.x4.shared.b16 {%0,%1,%2,%3}, [%4];"
                 : "=r"(r0), "=r"(r1), "=r"(r2), "=r"(r3) : "r"(addr));
}
__device__ __forceinline__ void mma_bf16(float* c, const uint32_t* a, uint32_t b0, uint32_t b1) {
    asm volatile("mma.sync.aligned.m16n8k16.row.col.f32.bf16.bf16.f32 "
                 "{%0,%1,%2,%3}, {%4,%5,%6,%7}, {%8,%9}, {%0,%1,%2,%3};"
                 : "+f"(c[0]), "+f"(c[1]), "+f"(c[2]), "+f"(c[3])
                 : "r"(a[0]), "r"(a[1]), "r"(a[2]), "r"(a[3]), "r"(b0), "r"(b1));
}
__device__ __forceinline__ void cp_async16(uint32_t smem_addr, const void* gptr, uint32_t src_sz) {
    asm volatile("cp.async.cg.shared.global [%0], [%1], 16, %2;"
                 :: "r"(smem_addr), "l"(gptr), "r"(src_sz) : "memory");
}
#define CP_COMMIT() asm volatile("cp.async.commit_group;" ::: "memory")
#define CP_WAIT(n)  asm volatile("cp.async.wait_group %0;" :: "n"(n) : "memory")
__device__ __forceinline__ uint32_t smem_u32(const void* p) {
    uint32_t a;
    asm("{ .reg .u64 t; cvta.to.shared.u64 t, %1; cvt.u32.u64 %0, t; }" : "=r"(a) : "l"(p));
    return a;
}

// ---------------------------------------------------------------------------
// 0. zero-init
__global__ void init_kernel(int n_nodes, int n_graphs) {
    int i = blockIdx.x * blockDim.x + threadIdx.x;
    int total = n_nodes + n_graphs + n_graphs * HID;
    for (; i < total; i += gridDim.x * blockDim.x) {
        if (i < n_nodes) g_counts[i] = 0;
        else if (i < n_nodes + n_graphs) g_gcnt[i - n_nodes] = 0;
        else g_sums[i - n_nodes - n_graphs] = 0.0f;
    }
}
// 1. in-degree
__global__ void count_kernel(const int* __restrict__ ei, int E) {
    int e = blockIdx.x * blockDim.x + threadIdx.x;
    if (e < E) atomicAdd(&g_counts[ei[E + e]], 1);
}
// 2. single-block scan -> offsets + deg_inv_sqrt
__global__ void scan_kernel(int n) {
    __shared__ int smem[1024];
    __shared__ int carry;
    if (threadIdx.x == 0) carry = 0;
    __syncthreads();
    for (int base = 0; base < n; base += 1024) {
        int i = base + (int)threadIdx.x;
        int v = (i < n) ? g_counts[i] : 0;
        smem[threadIdx.x] = v;
        __syncthreads();
        #pragma unroll
        for (int d = 1; d < 1024; d <<= 1) {
            int t = (threadIdx.x >= (unsigned)d) ? smem[threadIdx.x - d] : 0;
            __syncthreads();
            smem[threadIdx.x] += t;
            __syncthreads();
        }
        int incl = smem[threadIdx.x];
        if (i < n) {
            int excl = carry + incl - v;
            g_offs[i] = excl;
            g_wptr[i] = excl;
            g_dis[i]  = rsqrtf(1.0f + (float)v);
        }
        __syncthreads();
        if (threadIdx.x == 1023) carry += smem[1023];
        __syncthreads();
    }
    if (threadIdx.x == 0) g_offs[n] = carry;
}
// 3. fill CSR
__global__ void fill_kernel(const int* __restrict__ ei, int E) {
    int e = blockIdx.x * blockDim.x + threadIdx.x;
    if (e < E) {
        int s = ei[e], d = ei[E + e];
        g_csr[atomicAdd(&g_wptr[d], 1)] = s;
    }
}

// ---------------------------------------------------------------------------
// 4. aggregation + fused bf16 hi/lo split
template <int F>
__global__ void agg_split(const float* __restrict__ h,
                          __nv_bfloat16* __restrict__ oh, __nv_bfloat16* __restrict__ ol) {
    int node = blockIdx.x;
    int f = threadIdx.x;  // blockDim == F
    float di = g_dis[node];
    float acc = di * h[(size_t)node * F + f];
    int e0 = g_offs[node], e1 = g_offs[node + 1];
    __shared__ int   s_src[64];
    __shared__ float s_w[64];
    for (int base = e0; base < e1; base += 64) {
        int n = min(64, e1 - base);
        if (f < n) {
            int s = g_csr[base + f];
            s_src[f] = s;
            s_w[f]   = g_dis[s];
        }
        __syncthreads();
        for (int j = 0; j < n; j++)
            acc += s_w[j] * h[(size_t)s_src[j] * F + f];
        __syncthreads();
    }
    float v = di * acc;
    __nv_bfloat16 hi = __float2bfloat16(v);
    float lo = v - __bfloat162float(hi);
    size_t idx = (size_t)node * F + f;
    oh[idx] = hi;
    ol[idx] = __float2bfloat16(lo);
}

// 5. weight split + transpose: W[K,N] fp32 -> Wh/Wl [N,K] bf16 (K-major)
__global__ void wsplit_kernel(const float* __restrict__ W,
                              __nv_bfloat16* __restrict__ Wh, __nv_bfloat16* __restrict__ Wl,
                              int K, int N) {
    int idx = blockIdx.x * blockDim.x + threadIdx.x;
    if (idx < K * N) {
        int k = idx / N, n = idx % N;
        float w = W[idx];
        __nv_bfloat16 hi = __float2bfloat16(w);
        Wh[n * K + k] = hi;
        Wl[n * K + k] = __float2bfloat16(w - __bfloat162float(hi));
    }
}

// ---------------------------------------------------------------------------
// 6. tensor-core GEMM via mma.sync (base ISA):
//    C[M,256] = relu( (Ah+Al)[M,K] @ (Bh+Bl)^T + bias ),  B stored [N,K] K-major.
//    3-term split: Ah.Bh + Ah.Bl + Al.Bh.
//    CTA tile 128x128, 256 thr (2x4 warps, 64x32 warp tile), K slabs of 16,
//    cp.async double buffer, XOR-swizzled smem for conflict-free ldmatrix.
#define PITCH_B 32   // bytes per smem row (16 bf16)
#define TILE_B  4096 // 128 rows * 32B
#define STAGE_B 16384

__global__ void __launch_bounds__(256)
gemm_tc(const __nv_bfloat16* __restrict__ Ah, const __nv_bfloat16* __restrict__ Al,
        const __nv_bfloat16* __restrict__ Bh, const __nv_bfloat16* __restrict__ Bl,
        const float* __restrict__ bias, float* __restrict__ C, int M, int K) {
    __shared__ __align__(1024) char smem[2 * STAGE_B];
    uint32_t sbase = smem_u32(smem);

    int tid = threadIdx.x;
    int wid = tid >> 5, lane = tid & 31;
    int wm = wid >> 2, wn = wid & 3;            // warp grid 2x4
    int m0 = blockIdx.y * 128, n0 = blockIdx.x * 128;

    float acc[4][4][4];
    #pragma unroll
    for (int i = 0; i < 4; i++)
        #pragma unroll
        for (int j = 0; j < 4; j++)
            #pragma unroll
            for (int q = 0; q < 4; q++) acc[i][j][q] = 0.0f;

    int nk = K >> 4;

    // stage loader: tiles {0:Ah, 1:Al, 2:Bh, 3:Bl}, 16B chunk per (row, half)
    auto load_stage = [&](int stage, int k0) {
        uint32_t sb = sbase + stage * STAGE_B;
        #pragma unroll
        for (int i = 0; i < 4; i++) {
            int c = tid + i * 256;
            int tile = c >> 8, t = c & 255;
            int row = t >> 1, half = t & 1;
            uint32_t dst = sb + tile * TILE_B + row * PITCH_B +
                           ((half ^ ((row >> 2) & 1)) << 4);
            const __nv_bfloat16* src;
            uint32_t sz = 16;
            if (tile < 2) {
                int gr = m0 + row;
                int cr = gr < M ? gr : (M - 1);
                src = (tile == 0 ? Ah : Al) + (size_t)cr * K + k0 + half * 8;
                if (gr >= M) sz = 0;
            } else {
                src = (tile == 2 ? Bh : Bl) + (size_t)(n0 + row) * K + k0 + half * 8;
            }
            cp_async16(dst, src, sz);
        }
        CP_COMMIT();
    };

    load_stage(0, 0);

    int r = lane & 15, sel = lane >> 4;

    for (int s = 0; s < nk; s++) {
        if (s + 1 < nk) load_stage((s + 1) & 1, (s + 1) << 4);
        if (s + 1 < nk) { CP_WAIT(1); } else { CP_WAIT(0); }
        __syncthreads();

        uint32_t sb = sbase + (s & 1) * STAGE_B;
        uint32_t sAh = sb, sAl = sb + TILE_B, sBh = sb + 2 * TILE_B, sBl = sb + 3 * TILE_B;

        uint32_t ah[4][4], al[4][4];
        #pragma unroll
        for (int mi = 0; mi < 4; mi++) {
            int rowA = wm * 64 + mi * 16 + r;
            uint32_t off = rowA * PITCH_B + ((sel ^ ((rowA >> 2) & 1)) << 4);
            ldsm_x4(ah[mi][0], ah[mi][1], ah[mi][2], ah[mi][3], sAh + off);
            ldsm_x4(al[mi][0], al[mi][1], al[mi][2], al[mi][3], sAl + off);
        }
        uint32_t bh[2][4], bl[2][4];
        #pragma unroll
        for (int nj = 0; nj < 2; nj++) {
            int rowB = wn * 32 + nj * 16 + r;
            uint32_t off = rowB * PITCH_B + ((sel ^ ((rowB >> 2) & 1)) << 4);
            ldsm_x4(bh[nj][0], bh[nj][1], bh[nj][2], bh[nj][3], sBh + off);
            ldsm_x4(bl[nj][0], bl[nj][1], bl[nj][2], bl[nj][3], sBl + off);
        }
        #pragma unroll
        for (int mi = 0; mi < 4; mi++) {
            #pragma unroll
            for (int nn = 0; nn < 4; nn++) {
                int nj = nn >> 1, hi8 = nn & 1;
                uint32_t b0h = bh[nj][hi8], b1h = bh[nj][hi8 + 2];
                uint32_t b0l = bl[nj][hi8], b1l = bl[nj][hi8 + 2];
                mma_bf16(acc[mi][nn], ah[mi], b0h, b1h);
                mma_bf16(acc[mi][nn], ah[mi], b0l, b1l);
                mma_bf16(acc[mi][nn], al[mi], b0h, b1h);
            }
        }
        __syncthreads();
    }

    // epilogue: bias + relu
    int qr = lane >> 2, qc = lane & 3;
    #pragma unroll
    for (int nn = 0; nn < 4; nn++) {
        int col = n0 + wn * 32 + (nn >> 1) * 16 + (nn & 1) * 8 + qc * 2;
        float bz0 = __ldg(&bias[col]), bz1 = __ldg(&bias[col + 1]);
        #pragma unroll
        for (int mi = 0; mi < 4; mi++) {
            int row0 = m0 + wm * 64 + mi * 16 + qr;
            if (row0 < M) {
                float2 o;
                o.x = fmaxf(acc[mi][nn][0] + bz0, 0.f);
                o.y = fmaxf(acc[mi][nn][1] + bz1, 0.f);
                *(float2*)(C + (size_t)row0 * 256 + col) = o;
            }
            int row1 = row0 + 8;
            if (row1 < M) {
                float2 o;
                o.x = fmaxf(acc[mi][nn][2] + bz0, 0.f);
                o.y = fmaxf(acc[mi][nn][3] + bz1, 0.f);
                *(float2*)(C + (size_t)row1 * 256 + col) = o;
            }
        }
    }
}

// ---------------------------------------------------------------------------
// 7. mean-pool accumulation
__global__ void pool_kernel(const float* __restrict__ h, const int* __restrict__ batch) {
    int node = blockIdx.x;
    int g = batch[node];
    if (threadIdx.x == 0) atomicAdd(&g_gcnt[g], 1);
    atomicAdd(&g_sums[g * HID + threadIdx.x], h[(size_t)node * HID + threadIdx.x]);
}
// 8. head
__global__ void head_kernel(const float* __restrict__ molwt, const float* __restrict__ nrings,
                            const float* __restrict__ fcW1, const float* __restrict__ fcb1,
                            const float* __restrict__ fcW2, const float* __restrict__ fcb2,
                            float* __restrict__ out) {
    int g = blockIdx.x;
    __shared__ float hg[258];
    __shared__ float h1[196];
    int t = threadIdx.x;  // 256
    float c = fmaxf((float)g_gcnt[g], 1.0f);
    hg[t] = g_sums[g * HID + t] / c;
    if (t == 0) { hg[256] = molwt[g]; hg[257] = nrings[g]; }
    __syncthreads();
    if (t < 196) {
        float a = fcb1[t];
        #pragma unroll 4
        for (int k = 0; k < 258; k++) a += hg[k] * fcW1[k * 196 + t];
        h1[t] = fmaxf(a, 0.0f);
    }
    __syncthreads();
    if (t < 16) {
        float a = fcb2[t];
        #pragma unroll 4
        for (int k = 0; k < 196; k++) a += h1[k] * fcW2[k * 16 + t];
        out[g * 16 + t] = a;
    }
}

// ---------------------------------------------------------------------------
extern "C" void kernel_launch(void* const* d_in, const int* in_sizes, int n_in,
                              void* d_out, int out_size) {
    const float* x      = (const float*)d_in[0];
    const int*   ei     = (const int*)  d_in[1];
    const int*   batch  = (const int*)  d_in[2];
    const float* molwt  = (const float*)d_in[3];
    const float* nrings = (const float*)d_in[4];
    const float* W1 = (const float*)d_in[5];
    const float* b1 = (const float*)d_in[6];
    const float* W2 = (const float*)d_in[7];
    const float* b2 = (const float*)d_in[8];
    const float* W3 = (const float*)d_in[9];
    const float* b3 = (const float*)d_in[10];
    const float* fcW1 = (const float*)d_in[11];
    const float* fcb1 = (const float*)d_in[12];
    const float* fcW2 = (const float*)d_in[13];
    const float* fcb2 = (const float*)d_in[14];

    const int N = in_sizes[2];
    const int E = in_sizes[1] / 2;
    const int G = in_sizes[3];
    const int F_IN = in_sizes[0] / N;   // 128

    __nv_bfloat16 *Ah, *Al, *Wh1, *Wl1, *Wh2, *Wl2, *Wh3, *Wl3;
    float* bufB;
    cudaGetSymbolAddress((void**)&Ah, g_Ah);
    cudaGetSymbolAddress((void**)&Al, g_Al);
    cudaGetSymbolAddress((void**)&bufB, g_bufB);
    cudaGetSymbolAddress((void**)&Wh1, g_Wh1);
    cudaGetSymbolAddress((void**)&Wl1, g_Wl1);
    cudaGetSymbolAddress((void**)&Wh2, g_Wh2);
    cudaGetSymbolAddress((void**)&Wl2, g_Wl2);
    cudaGetSymbolAddress((void**)&Wh3, g_Wh3);
    cudaGetSymbolAddress((void**)&Wl3, g_Wl3);

    // graph structure
    init_kernel<<<256, 256>>>(N, G);
    count_kernel<<<(E + 255) / 256, 256>>>(ei, E);
    scan_kernel<<<1, 1024>>>(N);
    fill_kernel<<<(E + 255) / 256, 256>>>(ei, E);

    // weight splits (transposed, K-major)
    wsplit_kernel<<<(F_IN * 256 + 255) / 256, 256>>>(W1, Wh1, Wl1, F_IN, 256);
    wsplit_kernel<<<(256 * 256 + 255) / 256, 256>>>(W2, Wh2, Wl2, 256, 256);
    wsplit_kernel<<<(256 * 256 + 255) / 256, 256>>>(W3, Wh3, Wl3, 256, 256);

    dim3 ggrid(2, (N + 127) / 128);

    // layer 1
    agg_split<128><<<N, 128>>>(x, Ah, Al);
    gemm_tc<<<ggrid, 256>>>(Ah, Al, Wh1, Wl1, b1, bufB, N, F_IN);
    // layer 2
    agg_split<256><<<N, 256>>>(bufB, Ah, Al);
    gemm_tc<<<ggrid, 256>>>(Ah, Al, Wh2, Wl2, b2, bufB, N, HID);
    // layer 3
    agg_split<256><<<N, 256>>>(bufB, Ah, Al);
    gemm_tc<<<ggrid, 256>>>(Ah, Al, Wh3, Wl3, b3, bufB, N, HID);

    // pooling + head
    pool_kernel<<<N, 256>>>(bufB, batch);
    head_kernel<<<G, 256>>>(molwt, nrings, fcW1, fcb1, fcW2, fcb2, (float*)d_out);
}

// round 4
// speedup vs baseline: 1.6795x; 1.2788x over previous
#include <cuda_runtime.h>
#include <cuda_bf16.h>
#include <cstdint>
#include <math.h>

// Problem constants (fixed for this dataset)
#define MAXN 50000
#define MAXE 800000
#define MAXG 512
#define HID  256

// ---------------------------------------------------------------------------
// Scratch (__device__ globals: allocation-free per harness rules)
__device__ __nv_bfloat16 g_Ah[(size_t)MAXN * HID];   // agg output, bf16 hi
__device__ __nv_bfloat16 g_Al[(size_t)MAXN * HID];   // agg output, bf16 lo
__device__ float g_bufB[(size_t)MAXN * HID];         // post-GEMM hidden (fp32)
__device__ float g_dis[MAXN];
__device__ int   g_counts[MAXN];
__device__ int   g_offs[MAXN + 1];
__device__ int   g_wptr[MAXN];
__device__ int   g_csr[MAXE];
__device__ float g_sums[MAXG * HID];
__device__ int   g_gcnt[MAXG];
// split+transposed weights: [N=256 rows][K cols], K-major bf16
__device__ __nv_bfloat16 g_Wh1[256 * 128], g_Wl1[256 * 128];
__device__ __nv_bfloat16 g_Wh2[256 * 256], g_Wl2[256 * 256];
__device__ __nv_bfloat16 g_Wh3[256 * 256], g_Wl3[256 * 256];

// ---------------------------------------------------------------------------
// base-ISA tensor helpers (mma.sync / ldmatrix / cp.async — no sm_103a features)
__device__ __forceinline__ void ldsm_x4(uint32_t& r0, uint32_t& r1, uint32_t& r2, uint32_t& r3,
                                        uint32_t addr) {
    asm volatile("ldmatrix.sync.aligned.m8n8.x4.shared.b16 {%0,%1,%2,%3}, [%4];"
                 : "=r"(r0), "=r"(r1), "=r"(r2), "=r"(r3) : "r"(addr));
}
__device__ __forceinline__ void mma_bf16(float* c, const uint32_t* a, uint32_t b0, uint32_t b1) {
    asm volatile("mma.sync.aligned.m16n8k16.row.col.f32.bf16.bf16.f32 "
                 "{%0,%1,%2,%3}, {%4,%5,%6,%7}, {%8,%9}, {%0,%1,%2,%3};"
                 : "+f"(c[0]), "+f"(c[1]), "+f"(c[2]), "+f"(c[3])
                 : "r"(a[0]), "r"(a[1]), "r"(a[2]), "r"(a[3]), "r"(b0), "r"(b1));
}
__device__ __forceinline__ void cp_async16(uint32_t smem_addr, const void* gptr, uint32_t src_sz) {
    asm volatile("cp.async.cg.shared.global [%0], [%1], 16, %2;"
                 :: "r"(smem_addr), "l"(gptr), "r"(src_sz) : "memory");
}
#define CP_COMMIT() asm volatile("cp.async.commit_group;" ::: "memory")
#define CP_WAIT(n)  asm volatile("cp.async.wait_group %0;" :: "n"(n) : "memory")
__device__ __forceinline__ uint32_t smem_u32(const void* p) {
    uint32_t a;
    asm("{ .reg .u64 t; cvta.to.shared.u64 t, %1; cvt.u32.u64 %0, t; }" : "=r"(a) : "l"(p));
    return a;
}

// ---------------------------------------------------------------------------
// 0. zero-init
__global__ void init_kernel(int n_nodes, int n_graphs) {
    int i = blockIdx.x * blockDim.x + threadIdx.x;
    int total = n_nodes + n_graphs + n_graphs * HID;
    for (; i < total; i += gridDim.x * blockDim.x) {
        if (i < n_nodes) g_counts[i] = 0;
        else if (i < n_nodes + n_graphs) g_gcnt[i - n_nodes] = 0;
        else g_sums[i - n_nodes - n_graphs] = 0.0f;
    }
}
// 1. in-degree
__global__ void count_kernel(const int* __restrict__ ei, int E) {
    int e = blockIdx.x * blockDim.x + threadIdx.x;
    if (e < E) atomicAdd(&g_counts[ei[E + e]], 1);
}
// 1b. per-graph node counts
__global__ void gcnt_kernel(const int* __restrict__ batch, int N) {
    int i = blockIdx.x * blockDim.x + threadIdx.x;
    if (i < N) atomicAdd(&g_gcnt[batch[i]], 1);
}
// 2. single-block scan -> offsets + deg_inv_sqrt
__global__ void scan_kernel(int n) {
    __shared__ int smem[1024];
    __shared__ int carry;
    if (threadIdx.x == 0) carry = 0;
    __syncthreads();
    for (int base = 0; base < n; base += 1024) {
        int i = base + (int)threadIdx.x;
        int v = (i < n) ? g_counts[i] : 0;
        smem[threadIdx.x] = v;
        __syncthreads();
        #pragma unroll
        for (int d = 1; d < 1024; d <<= 1) {
            int t = (threadIdx.x >= (unsigned)d) ? smem[threadIdx.x - d] : 0;
            __syncthreads();
            smem[threadIdx.x] += t;
            __syncthreads();
        }
        int incl = smem[threadIdx.x];
        if (i < n) {
            int excl = carry + incl - v;
            g_offs[i] = excl;
            g_wptr[i] = excl;
            g_dis[i]  = rsqrtf(1.0f + (float)v);
        }
        __syncthreads();
        if (threadIdx.x == 1023) carry += smem[1023];
        __syncthreads();
    }
    if (threadIdx.x == 0) g_offs[n] = carry;
}
// 3. fill CSR
__global__ void fill_kernel(const int* __restrict__ ei, int E) {
    int e = blockIdx.x * blockDim.x + threadIdx.x;
    if (e < E) {
        int s = ei[e], d = ei[E + e];
        g_csr[atomicAdd(&g_wptr[d], 1)] = s;
    }
}

// ---------------------------------------------------------------------------
// 4. warp-per-node aggregation + fused bf16 hi/lo split.
//    Each lane owns F/32 features via float4; edge (src, w) broadcast by shfl.
template <int F>
__global__ void agg_split_v2(const float* __restrict__ h,
                             __nv_bfloat16* __restrict__ oh,
                             __nv_bfloat16* __restrict__ ol, int N) {
    constexpr int V = F / 128;                 // float4 per lane: 1 (F=128) or 2 (F=256)
    int node = blockIdx.x * (blockDim.x >> 5) + (threadIdx.x >> 5);
    int lane = threadIdx.x & 31;
    if (node >= N) return;

    float di = g_dis[node];
    float4 acc[V];
    const float4* hrow = (const float4*)(h + (size_t)node * F);
    #pragma unroll
    for (int v = 0; v < V; v++) {
        float4 t = hrow[lane + v * 32];
        acc[v].x = di * t.x; acc[v].y = di * t.y;
        acc[v].z = di * t.z; acc[v].w = di * t.w;
    }

    int e0 = g_offs[node], e1 = g_offs[node + 1];
    for (int base = e0; base < e1; base += 32) {
        int e = base + lane;
        int s = 0; float w = 0.0f;
        if (e < e1) { s = g_csr[e]; w = g_dis[s]; }
        int cnt = min(32, e1 - base);
        #pragma unroll 4
        for (int j = 0; j < cnt; j++) {
            int   sj = __shfl_sync(0xffffffffu, s, j);
            float wj = __shfl_sync(0xffffffffu, w, j);
            const float4* srow = (const float4*)(h + (size_t)sj * F);
            #pragma unroll
            for (int v = 0; v < V; v++) {
                float4 t = srow[lane + v * 32];
                acc[v].x += wj * t.x; acc[v].y += wj * t.y;
                acc[v].z += wj * t.z; acc[v].w += wj * t.w;
            }
        }
    }

    #pragma unroll
    for (int v = 0; v < V; v++) {
        float4 r;
        r.x = di * acc[v].x; r.y = di * acc[v].y;
        r.z = di * acc[v].z; r.w = di * acc[v].w;
        __nv_bfloat162 h01 = __floats2bfloat162_rn(r.x, r.y);
        __nv_bfloat162 h23 = __floats2bfloat162_rn(r.z, r.w);
        float2 f01 = __bfloat1622float2(h01);
        float2 f23 = __bfloat1622float2(h23);
        __nv_bfloat162 l01 = __floats2bfloat162_rn(r.x - f01.x, r.y - f01.y);
        __nv_bfloat162 l23 = __floats2bfloat162_rn(r.z - f23.x, r.w - f23.y);
        size_t idx = (size_t)node * F + (lane + v * 32) * 4;
        uint2 uh, ul;
        uh.x = *(uint32_t*)&h01; uh.y = *(uint32_t*)&h23;
        ul.x = *(uint32_t*)&l01; ul.y = *(uint32_t*)&l23;
        *(uint2*)(oh + idx) = uh;
        *(uint2*)(ol + idx) = ul;
    }
}

// 5. weight split + transpose: W[K,N] fp32 -> Wh/Wl [N,K] bf16 (K-major)
__global__ void wsplit_kernel(const float* __restrict__ W,
                              __nv_bfloat16* __restrict__ Wh, __nv_bfloat16* __restrict__ Wl,
                              int K, int N) {
    int idx = blockIdx.x * blockDim.x + threadIdx.x;
    if (idx < K * N) {
        int k = idx / N, n = idx % N;
        float w = W[idx];
        __nv_bfloat16 hi = __float2bfloat16(w);
        Wh[n * K + k] = hi;
        Wl[n * K + k] = __float2bfloat16(w - __bfloat162float(hi));
    }
}

// ---------------------------------------------------------------------------
// 6. tensor-core GEMM via mma.sync: C = relu((Ah+Al) @ (Bh+Bl)^T + bias)
//    3-term split. CTA 128x128, 256 thr, K slabs of 16, cp.async double buffer.
//    POOL=true: skip C store, atomically accumulate into g_sums (graph pooling).
#define PITCH_B 32
#define TILE_B  4096
#define STAGE_B 16384

template <bool POOL>
__global__ void __launch_bounds__(256)
gemm_tc(const __nv_bfloat16* __restrict__ Ah, const __nv_bfloat16* __restrict__ Al,
        const __nv_bfloat16* __restrict__ Bh, const __nv_bfloat16* __restrict__ Bl,
        const float* __restrict__ bias, float* __restrict__ C,
        const int* __restrict__ batch, int M, int K) {
    __shared__ __align__(1024) char smem[2 * STAGE_B];
    uint32_t sbase = smem_u32(smem);

    int tid = threadIdx.x;
    int wid = tid >> 5, lane = tid & 31;
    int wm = wid >> 2, wn = wid & 3;
    int m0 = blockIdx.y * 128, n0 = blockIdx.x * 128;

    float acc[4][4][4];
    #pragma unroll
    for (int i = 0; i < 4; i++)
        #pragma unroll
        for (int j = 0; j < 4; j++)
            #pragma unroll
            for (int q = 0; q < 4; q++) acc[i][j][q] = 0.0f;

    int nk = K >> 4;

    auto load_stage = [&](int stage, int k0) {
        uint32_t sb = sbase + stage * STAGE_B;
        #pragma unroll
        for (int i = 0; i < 4; i++) {
            int c = tid + i * 256;
            int tile = c >> 8, t = c & 255;
            int row = t >> 1, half = t & 1;
            uint32_t dst = sb + tile * TILE_B + row * PITCH_B +
                           ((half ^ ((row >> 2) & 1)) << 4);
            const __nv_bfloat16* src;
            uint32_t sz = 16;
            if (tile < 2) {
                int gr = m0 + row;
                int cr = gr < M ? gr : (M - 1);
                src = (tile == 0 ? Ah : Al) + (size_t)cr * K + k0 + half * 8;
                if (gr >= M) sz = 0;
            } else {
                src = (tile == 2 ? Bh : Bl) + (size_t)(n0 + row) * K + k0 + half * 8;
            }
            cp_async16(dst, src, sz);
        }
        CP_COMMIT();
    };

    load_stage(0, 0);

    int r = lane & 15, sel = lane >> 4;

    for (int s = 0; s < nk; s++) {
        if (s + 1 < nk) load_stage((s + 1) & 1, (s + 1) << 4);
        if (s + 1 < nk) { CP_WAIT(1); } else { CP_WAIT(0); }
        __syncthreads();

        uint32_t sb = sbase + (s & 1) * STAGE_B;
        uint32_t sAh = sb, sAl = sb + TILE_B, sBh = sb + 2 * TILE_B, sBl = sb + 3 * TILE_B;

        uint32_t ah[4][4], al[4][4];
        #pragma unroll
        for (int mi = 0; mi < 4; mi++) {
            int rowA = wm * 64 + mi * 16 + r;
            uint32_t off = rowA * PITCH_B + ((sel ^ ((rowA >> 2) & 1)) << 4);
            ldsm_x4(ah[mi][0], ah[mi][1], ah[mi][2], ah[mi][3], sAh + off);
            ldsm_x4(al[mi][0], al[mi][1], al[mi][2], al[mi][3], sAl + off);
        }
        uint32_t bh[2][4], bl[2][4];
        #pragma unroll
        for (int nj = 0; nj < 2; nj++) {
            int rowB = wn * 32 + nj * 16 + r;
            uint32_t off = rowB * PITCH_B + ((sel ^ ((rowB >> 2) & 1)) << 4);
            ldsm_x4(bh[nj][0], bh[nj][1], bh[nj][2], bh[nj][3], sBh + off);
            ldsm_x4(bl[nj][0], bl[nj][1], bl[nj][2], bl[nj][3], sBl + off);
        }
        #pragma unroll
        for (int mi = 0; mi < 4; mi++) {
            #pragma unroll
            for (int nn = 0; nn < 4; nn++) {
                int nj = nn >> 1, hi8 = nn & 1;
                uint32_t b0h = bh[nj][hi8], b1h = bh[nj][hi8 + 2];
                uint32_t b0l = bl[nj][hi8], b1l = bl[nj][hi8 + 2];
                mma_bf16(acc[mi][nn], ah[mi], b0h, b1h);
                mma_bf16(acc[mi][nn], ah[mi], b0l, b1l);
                mma_bf16(acc[mi][nn], al[mi], b0h, b1h);
            }
        }
        __syncthreads();
    }

    // epilogue
    int qr = lane >> 2, qc = lane & 3;
    #pragma unroll
    for (int nn = 0; nn < 4; nn++) {
        int col = n0 + wn * 32 + (nn >> 1) * 16 + (nn & 1) * 8 + qc * 2;
        float bz0 = __ldg(&bias[col]), bz1 = __ldg(&bias[col + 1]);
        #pragma unroll
        for (int mi = 0; mi < 4; mi++) {
            int row0 = m0 + wm * 64 + mi * 16 + qr;
            if (row0 < M) {
                float v0 = fmaxf(acc[mi][nn][0] + bz0, 0.f);
                float v1 = fmaxf(acc[mi][nn][1] + bz1, 0.f);
                if (POOL) {
                    int g = __ldg(&batch[row0]);
                    atomicAdd(&g_sums[g * HID + col],     v0);
                    atomicAdd(&g_sums[g * HID + col + 1], v1);
                } else {
                    *(float2*)(C + (size_t)row0 * 256 + col) = make_float2(v0, v1);
                }
            }
            int row1 = row0 + 8;
            if (row1 < M) {
                float v2 = fmaxf(acc[mi][nn][2] + bz0, 0.f);
                float v3 = fmaxf(acc[mi][nn][3] + bz1, 0.f);
                if (POOL) {
                    int g = __ldg(&batch[row1]);
                    atomicAdd(&g_sums[g * HID + col],     v2);
                    atomicAdd(&g_sums[g * HID + col + 1], v3);
                } else {
                    *(float2*)(C + (size_t)row1 * 256 + col) = make_float2(v2, v3);
                }
            }
        }
    }
}

// ---------------------------------------------------------------------------
// 7. head: mean, concat, fc1(relu), fc2 -> out[G,16]
__global__ void head_kernel(const float* __restrict__ molwt, const float* __restrict__ nrings,
                            const float* __restrict__ fcW1, const float* __restrict__ fcb1,
                            const float* __restrict__ fcW2, const float* __restrict__ fcb2,
                            float* __restrict__ out) {
    int g = blockIdx.x;
    __shared__ float hg[258];
    __shared__ float h1[196];
    int t = threadIdx.x;  // 256
    float c = fmaxf((float)g_gcnt[g], 1.0f);
    hg[t] = g_sums[g * HID + t] / c;
    if (t == 0) { hg[256] = molwt[g]; hg[257] = nrings[g]; }
    __syncthreads();
    if (t < 196) {
        float a = fcb1[t];
        #pragma unroll 4
        for (int k = 0; k < 258; k++) a += hg[k] * fcW1[k * 196 + t];
        h1[t] = fmaxf(a, 0.0f);
    }
    __syncthreads();
    if (t < 16) {
        float a = fcb2[t];
        #pragma unroll 4
        for (int k = 0; k < 196; k++) a += h1[k] * fcW2[k * 16 + t];
        out[g * 16 + t] = a;
    }
}

// ---------------------------------------------------------------------------
extern "C" void kernel_launch(void* const* d_in, const int* in_sizes, int n_in,
                              void* d_out, int out_size) {
    const float* x      = (const float*)d_in[0];
    const int*   ei     = (const int*)  d_in[1];
    const int*   batch  = (const int*)  d_in[2];
    const float* molwt  = (const float*)d_in[3];
    const float* nrings = (const float*)d_in[4];
    const float* W1 = (const float*)d_in[5];
    const float* b1 = (const float*)d_in[6];
    const float* W2 = (const float*)d_in[7];
    const float* b2 = (const float*)d_in[8];
    const float* W3 = (const float*)d_in[9];
    const float* b3 = (const float*)d_in[10];
    const float* fcW1 = (const float*)d_in[11];
    const float* fcb1 = (const float*)d_in[12];
    const float* fcW2 = (const float*)d_in[13];
    const float* fcb2 = (const float*)d_in[14];

    const int N = in_sizes[2];
    const int E = in_sizes[1] / 2;
    const int G = in_sizes[3];
    const int F_IN = in_sizes[0] / N;   // 128

    __nv_bfloat16 *Ah, *Al, *Wh1, *Wl1, *Wh2, *Wl2, *Wh3, *Wl3;
    float* bufB;
    cudaGetSymbolAddress((void**)&Ah, g_Ah);
    cudaGetSymbolAddress((void**)&Al, g_Al);
    cudaGetSymbolAddress((void**)&bufB, g_bufB);
    cudaGetSymbolAddress((void**)&Wh1, g_Wh1);
    cudaGetSymbolAddress((void**)&Wl1, g_Wl1);
    cudaGetSymbolAddress((void**)&Wh2, g_Wh2);
    cudaGetSymbolAddress((void**)&Wl2, g_Wl2);
    cudaGetSymbolAddress((void**)&Wh3, g_Wh3);
    cudaGetSymbolAddress((void**)&Wl3, g_Wl3);

    // graph structure
    init_kernel<<<256, 256>>>(N, G);
    count_kernel<<<(E + 255) / 256, 256>>>(ei, E);
    gcnt_kernel<<<(N + 255) / 256, 256>>>(batch, N);
    scan_kernel<<<1, 1024>>>(N);
    fill_kernel<<<(E + 255) / 256, 256>>>(ei, E);

    // weight splits (transposed, K-major)
    wsplit_kernel<<<(F_IN * 256 + 255) / 256, 256>>>(W1, Wh1, Wl1, F_IN, 256);
    wsplit_kernel<<<(256 * 256 + 255) / 256, 256>>>(W2, Wh2, Wl2, 256, 256);
    wsplit_kernel<<<(256 * 256 + 255) / 256, 256>>>(W3, Wh3, Wl3, 256, 256);

    dim3 ggrid(2, (N + 127) / 128);
    int aggblocks = (N + 7) / 8;   // 8 warps / block

    // layer 1
    agg_split_v2<128><<<aggblocks, 256>>>(x, Ah, Al, N);
    gemm_tc<false><<<ggrid, 256>>>(Ah, Al, Wh1, Wl1, b1, bufB, nullptr, N, F_IN);
    // layer 2
    agg_split_v2<256><<<aggblocks, 256>>>(bufB, Ah, Al, N);
    gemm_tc<false><<<ggrid, 256>>>(Ah, Al, Wh2, Wl2, b2, bufB, nullptr, N, HID);
    // layer 3 (pooling fused into epilogue)
    agg_split_v2<256><<<aggblocks, 256>>>(bufB, Ah, Al, N);
    gemm_tc<true><<<ggrid, 256>>>(Ah, Al, Wh3, Wl3, b3, nullptr, batch, N, HID);

    // head
    head_kernel<<<G, 256>>>(molwt, nrings, fcW1, fcb1, fcW2, fcb2, (float*)d_out);
}

// round 5
// speedup vs baseline: 1.9480x; 1.1599x over previous
#include <cuda_runtime.h>
#include <cuda_bf16.h>
#include <cstdint>
#include <math.h>

// Problem constants (fixed for this dataset)
#define MAXN 50000
#define MAXE 800000
#define MAXG 512
#define HID  256

// ---------------------------------------------------------------------------
// Scratch (__device__ globals: allocation-free per harness rules)
__device__ __nv_bfloat16 g_Ah[(size_t)MAXN * HID];   // agg output, bf16 hi
__device__ __nv_bfloat16 g_Al[(size_t)MAXN * HID];   // agg output, bf16 lo
__device__ float g_bufB[(size_t)MAXN * HID];         // post-GEMM hidden (fp32)
__device__ float g_dis[MAXN];
__device__ int   g_counts[MAXN];
__device__ int   g_offs[MAXN + 1];
__device__ int   g_wptr[MAXN];
__device__ int   g_csr[MAXE];
__device__ float g_sums[MAXG * HID];
__device__ int   g_gcnt[MAXG];
__device__ int   g_bsum[64];                          // block sums for scan
// split+transposed weights: [N=256 rows][K cols], K-major bf16
__device__ __nv_bfloat16 g_Wh1[256 * 128], g_Wl1[256 * 128];
__device__ __nv_bfloat16 g_Wh2[256 * 256], g_Wl2[256 * 256];
__device__ __nv_bfloat16 g_Wh3[256 * 256], g_Wl3[256 * 256];

// ---------------------------------------------------------------------------
// base-ISA tensor helpers (mma.sync / ldmatrix / cp.async — no sm_103a features)
__device__ __forceinline__ void ldsm_x4(uint32_t& r0, uint32_t& r1, uint32_t& r2, uint32_t& r3,
                                        uint32_t addr) {
    asm volatile("ldmatrix.sync.aligned.m8n8.x4.shared.b16 {%0,%1,%2,%3}, [%4];"
                 : "=r"(r0), "=r"(r1), "=r"(r2), "=r"(r3) : "r"(addr));
}
__device__ __forceinline__ void mma_bf16(float* c, const uint32_t* a, uint32_t b0, uint32_t b1) {
    asm volatile("mma.sync.aligned.m16n8k16.row.col.f32.bf16.bf16.f32 "
                 "{%0,%1,%2,%3}, {%4,%5,%6,%7}, {%8,%9}, {%0,%1,%2,%3};"
                 : "+f"(c[0]), "+f"(c[1]), "+f"(c[2]), "+f"(c[3])
                 : "r"(a[0]), "r"(a[1]), "r"(a[2]), "r"(a[3]), "r"(b0), "r"(b1));
}
__device__ __forceinline__ void cp_async16(uint32_t smem_addr, const void* gptr, uint32_t src_sz) {
    asm volatile("cp.async.cg.shared.global [%0], [%1], 16, %2;"
                 :: "r"(smem_addr), "l"(gptr), "r"(src_sz) : "memory");
}
#define CP_COMMIT() asm volatile("cp.async.commit_group;" ::: "memory")
#define CP_WAIT(n)  asm volatile("cp.async.wait_group %0;" :: "n"(n) : "memory")
__device__ __forceinline__ uint32_t smem_u32(const void* p) {
    uint32_t a;
    asm("{ .reg .u64 t; cvta.to.shared.u64 t, %1; cvt.u32.u64 %0, t; }" : "=r"(a) : "l"(p));
    return a;
}

// ---------------------------------------------------------------------------
// 0. zero-init
__global__ void init_kernel(int n_nodes, int n_graphs) {
    int i = blockIdx.x * blockDim.x + threadIdx.x;
    int total = n_nodes + n_graphs + n_graphs * HID;
    for (; i < total; i += gridDim.x * blockDim.x) {
        if (i < n_nodes) g_counts[i] = 0;
        else if (i < n_nodes + n_graphs) g_gcnt[i - n_nodes] = 0;
        else g_sums[i - n_nodes - n_graphs] = 0.0f;
    }
}
// 1. in-degree
__global__ void count_kernel(const int* __restrict__ ei, int E) {
    int e = blockIdx.x * blockDim.x + threadIdx.x;
    if (e < E) atomicAdd(&g_counts[ei[E + e]], 1);
}
// 1b. per-graph node counts
__global__ void gcnt_kernel(const int* __restrict__ batch, int N) {
    int i = blockIdx.x * blockDim.x + threadIdx.x;
    if (i < N) atomicAdd(&g_gcnt[batch[i]], 1);
}

// ---------------------------------------------------------------------------
// 2. three-phase multi-block exclusive scan of g_counts
// phase 1: per-block (1024) reduce -> g_bsum
__global__ void scan_p1(int n) {
    int i = blockIdx.x * 1024 + threadIdx.x;
    int v = (i < n) ? g_counts[i] : 0;
    __shared__ int sw[32];
    int lane = threadIdx.x & 31, wid = threadIdx.x >> 5;
    int s = v;
    #pragma unroll
    for (int o = 16; o > 0; o >>= 1) s += __shfl_down_sync(0xffffffffu, s, o);
    if (lane == 0) sw[wid] = s;
    __syncthreads();
    if (wid == 0) {
        int t = sw[lane];
        #pragma unroll
        for (int o = 16; o > 0; o >>= 1) t += __shfl_down_sync(0xffffffffu, t, o);
        if (lane == 0) g_bsum[blockIdx.x] = t;
    }
}
// phase 2: one block (64 thr) exclusive-scans block sums; writes offs[n]=total
__global__ void scan_p2(int nb, int n) {
    int lane = threadIdx.x;  // 64 threads
    __shared__ int sm[64];
    int v = (lane < nb) ? g_bsum[lane] : 0;
    sm[lane] = v;
    __syncthreads();
    #pragma unroll
    for (int d = 1; d < 64; d <<= 1) {
        int t = (lane >= d) ? sm[lane - d] : 0;
        __syncthreads();
        sm[lane] += t;
        __syncthreads();
    }
    if (lane < nb) g_bsum[lane] = sm[lane] - v;   // exclusive
    if (lane == nb - 1) g_offs[n] = sm[lane];     // inclusive total
}
// phase 3: per-block inclusive scan + base -> offs/wptr/dis
__global__ void scan_p3(int n) {
    int base = g_bsum[blockIdx.x];
    int i = blockIdx.x * 1024 + threadIdx.x;
    int v = (i < n) ? g_counts[i] : 0;
    __shared__ int sw[32];
    int lane = threadIdx.x & 31, wid = threadIdx.x >> 5;
    int inc = v;
    #pragma unroll
    for (int o = 1; o < 32; o <<= 1) {
        int t = __shfl_up_sync(0xffffffffu, inc, o);
        if (lane >= o) inc += t;
    }
    if (lane == 31) sw[wid] = inc;
    __syncthreads();
    if (wid == 0) {
        int t = sw[lane];
        #pragma unroll
        for (int o = 1; o < 32; o <<= 1) {
            int u = __shfl_up_sync(0xffffffffu, t, o);
            if (lane >= o) t += u;
        }
        sw[lane] = t;
    }
    __syncthreads();
    int excl = base + inc - v + (wid > 0 ? sw[wid - 1] : 0);
    if (i < n) {
        g_offs[i] = excl;
        g_wptr[i] = excl;
        g_dis[i]  = rsqrtf(1.0f + (float)v);
    }
}

// 3. fill CSR
__global__ void fill_kernel(const int* __restrict__ ei, int E) {
    int e = blockIdx.x * blockDim.x + threadIdx.x;
    if (e < E) {
        int s = ei[e], d = ei[E + e];
        g_csr[atomicAdd(&g_wptr[d], 1)] = s;
    }
}

// ---------------------------------------------------------------------------
// 4. warp-per-node aggregation + fused bf16 hi/lo split.
template <int F>
__global__ void agg_split_v2(const float* __restrict__ h,
                             __nv_bfloat16* __restrict__ oh,
                             __nv_bfloat16* __restrict__ ol, int N) {
    constexpr int V = F / 128;
    int node = blockIdx.x * (blockDim.x >> 5) + (threadIdx.x >> 5);
    int lane = threadIdx.x & 31;
    if (node >= N) return;

    float di = g_dis[node];
    float4 acc[V];
    const float4* hrow = (const float4*)(h + (size_t)node * F);
    #pragma unroll
    for (int v = 0; v < V; v++) {
        float4 t = hrow[lane + v * 32];
        acc[v].x = di * t.x; acc[v].y = di * t.y;
        acc[v].z = di * t.z; acc[v].w = di * t.w;
    }

    int e0 = g_offs[node], e1 = g_offs[node + 1];
    for (int base = e0; base < e1; base += 32) {
        int e = base + lane;
        int s = 0; float w = 0.0f;
        if (e < e1) { s = g_csr[e]; w = g_dis[s]; }
        int cnt = min(32, e1 - base);
        #pragma unroll 4
        for (int j = 0; j < cnt; j++) {
            int   sj = __shfl_sync(0xffffffffu, s, j);
            float wj = __shfl_sync(0xffffffffu, w, j);
            const float4* srow = (const float4*)(h + (size_t)sj * F);
            #pragma unroll
            for (int v = 0; v < V; v++) {
                float4 t = srow[lane + v * 32];
                acc[v].x += wj * t.x; acc[v].y += wj * t.y;
                acc[v].z += wj * t.z; acc[v].w += wj * t.w;
            }
        }
    }

    #pragma unroll
    for (int v = 0; v < V; v++) {
        float4 r;
        r.x = di * acc[v].x; r.y = di * acc[v].y;
        r.z = di * acc[v].z; r.w = di * acc[v].w;
        __nv_bfloat162 h01 = __floats2bfloat162_rn(r.x, r.y);
        __nv_bfloat162 h23 = __floats2bfloat162_rn(r.z, r.w);
        float2 f01 = __bfloat1622float2(h01);
        float2 f23 = __bfloat1622float2(h23);
        __nv_bfloat162 l01 = __floats2bfloat162_rn(r.x - f01.x, r.y - f01.y);
        __nv_bfloat162 l23 = __floats2bfloat162_rn(r.z - f23.x, r.w - f23.y);
        size_t idx = (size_t)node * F + (lane + v * 32) * 4;
        uint2 uh, ul;
        uh.x = *(uint32_t*)&h01; uh.y = *(uint32_t*)&h23;
        ul.x = *(uint32_t*)&l01; ul.y = *(uint32_t*)&l23;
        *(uint2*)(oh + idx) = uh;
        *(uint2*)(ol + idx) = ul;
    }
}

// 5. weight split + transpose: W[K,N] fp32 -> Wh/Wl [N,K] bf16 (K-major)
__global__ void wsplit_kernel(const float* __restrict__ W,
                              __nv_bfloat16* __restrict__ Wh, __nv_bfloat16* __restrict__ Wl,
                              int K, int N) {
    int idx = blockIdx.x * blockDim.x + threadIdx.x;
    if (idx < K * N) {
        int k = idx / N, n = idx % N;
        float w = W[idx];
        __nv_bfloat16 hi = __float2bfloat16(w);
        Wh[n * K + k] = hi;
        Wl[n * K + k] = __float2bfloat16(w - __bfloat162float(hi));
    }
}

// ---------------------------------------------------------------------------
// 6. tensor-core GEMM via mma.sync: C = relu((Ah+Al) @ (Bh+Bl)^T + bias)
//    3-term split. CTA 128x128, 256 thr, K slabs of 16, cp.async double buffer.
//    POOL=true: skip C store, atomically accumulate into g_sums (graph pooling).
#define PITCH_B 32
#define TILE_B  4096
#define STAGE_B 16384

template <bool POOL>
__global__ void __launch_bounds__(256)
gemm_tc(const __nv_bfloat16* __restrict__ Ah, const __nv_bfloat16* __restrict__ Al,
        const __nv_bfloat16* __restrict__ Bh, const __nv_bfloat16* __restrict__ Bl,
        const float* __restrict__ bias, float* __restrict__ C,
        const int* __restrict__ batch, int M, int K) {
    __shared__ __align__(1024) char smem[2 * STAGE_B];
    uint32_t sbase = smem_u32(smem);

    int tid = threadIdx.x;
    int wid = tid >> 5, lane = tid & 31;
    int wm = wid >> 2, wn = wid & 3;
    int m0 = blockIdx.y * 128, n0 = blockIdx.x * 128;

    float acc[4][4][4];
    #pragma unroll
    for (int i = 0; i < 4; i++)
        #pragma unroll
        for (int j = 0; j < 4; j++)
            #pragma unroll
            for (int q = 0; q < 4; q++) acc[i][j][q] = 0.0f;

    int nk = K >> 4;

    auto load_stage = [&](int stage, int k0) {
        uint32_t sb = sbase + stage * STAGE_B;
        #pragma unroll
        for (int i = 0; i < 4; i++) {
            int c = tid + i * 256;
            int tile = c >> 8, t = c & 255;
            int row = t >> 1, half = t & 1;
            uint32_t dst = sb + tile * TILE_B + row * PITCH_B +
                           ((half ^ ((row >> 2) & 1)) << 4);
            const __nv_bfloat16* src;
            uint32_t sz = 16;
            if (tile < 2) {
                int gr = m0 + row;
                int cr = gr < M ? gr : (M - 1);
                src = (tile == 0 ? Ah : Al) + (size_t)cr * K + k0 + half * 8;
                if (gr >= M) sz = 0;
            } else {
                src = (tile == 2 ? Bh : Bl) + (size_t)(n0 + row) * K + k0 + half * 8;
            }
            cp_async16(dst, src, sz);
        }
        CP_COMMIT();
    };

    load_stage(0, 0);

    int r = lane & 15, sel = lane >> 4;

    for (int s = 0; s < nk; s++) {
        if (s + 1 < nk) load_stage((s + 1) & 1, (s + 1) << 4);
        if (s + 1 < nk) { CP_WAIT(1); } else { CP_WAIT(0); }
        __syncthreads();

        uint32_t sb = sbase + (s & 1) * STAGE_B;
        uint32_t sAh = sb, sAl = sb + TILE_B, sBh = sb + 2 * TILE_B, sBl = sb + 3 * TILE_B;

        uint32_t ah[4][4], al[4][4];
        #pragma unroll
        for (int mi = 0; mi < 4; mi++) {
            int rowA = wm * 64 + mi * 16 + r;
            uint32_t off = rowA * PITCH_B + ((sel ^ ((rowA >> 2) & 1)) << 4);
            ldsm_x4(ah[mi][0], ah[mi][1], ah[mi][2], ah[mi][3], sAh + off);
            ldsm_x4(al[mi][0], al[mi][1], al[mi][2], al[mi][3], sAl + off);
        }
        uint32_t bh[2][4], bl[2][4];
        #pragma unroll
        for (int nj = 0; nj < 2; nj++) {
            int rowB = wn * 32 + nj * 16 + r;
            uint32_t off = rowB * PITCH_B + ((sel ^ ((rowB >> 2) & 1)) << 4);
            ldsm_x4(bh[nj][0], bh[nj][1], bh[nj][2], bh[nj][3], sBh + off);
            ldsm_x4(bl[nj][0], bl[nj][1], bl[nj][2], bl[nj][3], sBl + off);
        }
        #pragma unroll
        for (int mi = 0; mi < 4; mi++) {
            #pragma unroll
            for (int nn = 0; nn < 4; nn++) {
                int nj = nn >> 1, hi8 = nn & 1;
                uint32_t b0h = bh[nj][hi8], b1h = bh[nj][hi8 + 2];
                uint32_t b0l = bl[nj][hi8], b1l = bl[nj][hi8 + 2];
                mma_bf16(acc[mi][nn], ah[mi], b0h, b1h);
                mma_bf16(acc[mi][nn], ah[mi], b0l, b1l);
                mma_bf16(acc[mi][nn], al[mi], b0h, b1h);
            }
        }
        __syncthreads();
    }

    // epilogue
    int qr = lane >> 2, qc = lane & 3;
    #pragma unroll
    for (int nn = 0; nn < 4; nn++) {
        int col = n0 + wn * 32 + (nn >> 1) * 16 + (nn & 1) * 8 + qc * 2;
        float bz0 = __ldg(&bias[col]), bz1 = __ldg(&bias[col + 1]);
        #pragma unroll
        for (int mi = 0; mi < 4; mi++) {
            int row0 = m0 + wm * 64 + mi * 16 + qr;
            if (row0 < M) {
                float v0 = fmaxf(acc[mi][nn][0] + bz0, 0.f);
                float v1 = fmaxf(acc[mi][nn][1] + bz1, 0.f);
                if (POOL) {
                    int g = __ldg(&batch[row0]);
                    atomicAdd(&g_sums[g * HID + col],     v0);
                    atomicAdd(&g_sums[g * HID + col + 1], v1);
                } else {
                    *(float2*)(C + (size_t)row0 * 256 + col) = make_float2(v0, v1);
                }
            }
            int row1 = row0 + 8;
            if (row1 < M) {
                float v2 = fmaxf(acc[mi][nn][2] + bz0, 0.f);
                float v3 = fmaxf(acc[mi][nn][3] + bz1, 0.f);
                if (POOL) {
                    int g = __ldg(&batch[row1]);
                    atomicAdd(&g_sums[g * HID + col],     v2);
                    atomicAdd(&g_sums[g * HID + col + 1], v3);
                } else {
                    *(float2*)(C + (size_t)row1 * 256 + col) = make_float2(v2, v3);
                }
            }
        }
    }
}

// ---------------------------------------------------------------------------
// 7. head: mean, concat, fc1(relu), fc2 -> out[G,16]
__global__ void head_kernel(const float* __restrict__ molwt, const float* __restrict__ nrings,
                            const float* __restrict__ fcW1, const float* __restrict__ fcb1,
                            const float* __restrict__ fcW2, const float* __restrict__ fcb2,
                            float* __restrict__ out) {
    int g = blockIdx.x;
    __shared__ float hg[258];
    __shared__ float h1[196];
    int t = threadIdx.x;  // 256
    float c = fmaxf((float)g_gcnt[g], 1.0f);
    hg[t] = g_sums[g * HID + t] / c;
    if (t == 0) { hg[256] = molwt[g]; hg[257] = nrings[g]; }
    __syncthreads();
    if (t < 196) {
        float a = fcb1[t];
        #pragma unroll 4
        for (int k = 0; k < 258; k++) a += hg[k] * fcW1[k * 196 + t];
        h1[t] = fmaxf(a, 0.0f);
    }
    __syncthreads();
    if (t < 16) {
        float a = fcb2[t];
        #pragma unroll 4
        for (int k = 0; k < 196; k++) a += h1[k] * fcW2[k * 16 + t];
        out[g * 16 + t] = a;
    }
}

// ---------------------------------------------------------------------------
extern "C" void kernel_launch(void* const* d_in, const int* in_sizes, int n_in,
                              void* d_out, int out_size) {
    const float* x      = (const float*)d_in[0];
    const int*   ei     = (const int*)  d_in[1];
    const int*   batch  = (const int*)  d_in[2];
    const float* molwt  = (const float*)d_in[3];
    const float* nrings = (const float*)d_in[4];
    const float* W1 = (const float*)d_in[5];
    const float* b1 = (const float*)d_in[6];
    const float* W2 = (const float*)d_in[7];
    const float* b2 = (const float*)d_in[8];
    const float* W3 = (const float*)d_in[9];
    const float* b3 = (const float*)d_in[10];
    const float* fcW1 = (const float*)d_in[11];
    const float* fcb1 = (const float*)d_in[12];
    const float* fcW2 = (const float*)d_in[13];
    const float* fcb2 = (const float*)d_in[14];

    const int N = in_sizes[2];
    const int E = in_sizes[1] / 2;
    const int G = in_sizes[3];
    const int F_IN = in_sizes[0] / N;   // 128

    __nv_bfloat16 *Ah, *Al, *Wh1, *Wl1, *Wh2, *Wl2, *Wh3, *Wl3;
    float* bufB;
    cudaGetSymbolAddress((void**)&Ah, g_Ah);
    cudaGetSymbolAddress((void**)&Al, g_Al);
    cudaGetSymbolAddress((void**)&bufB, g_bufB);
    cudaGetSymbolAddress((void**)&Wh1, g_Wh1);
    cudaGetSymbolAddress((void**)&Wl1, g_Wl1);
    cudaGetSymbolAddress((void**)&Wh2, g_Wh2);
    cudaGetSymbolAddress((void**)&Wl2, g_Wl2);
    cudaGetSymbolAddress((void**)&Wh3, g_Wh3);
    cudaGetSymbolAddress((void**)&Wl3, g_Wl3);

    // graph structure
    int nb = (N + 1023) / 1024;
    init_kernel<<<256, 256>>>(N, G);
    count_kernel<<<(E + 255) / 256, 256>>>(ei, E);
    gcnt_kernel<<<(N + 255) / 256, 256>>>(batch, N);
    scan_p1<<<nb, 1024>>>(N);
    scan_p2<<<1, 64>>>(nb, N);
    scan_p3<<<nb, 1024>>>(N);
    fill_kernel<<<(E + 255) / 256, 256>>>(ei, E);

    // weight splits (transposed, K-major)
    wsplit_kernel<<<(F_IN * 256 + 255) / 256, 256>>>(W1, Wh1, Wl1, F_IN, 256);
    wsplit_kernel<<<(256 * 256 + 255) / 256, 256>>>(W2, Wh2, Wl2, 256, 256);
    wsplit_kernel<<<(256 * 256 + 255) / 256, 256>>>(W3, Wh3, Wl3, 256, 256);

    dim3 ggrid(2, (N + 127) / 128);
    int aggblocks = (N + 7) / 8;   // 8 warps / block

    // layer 1
    agg_split_v2<128><<<aggblocks, 256>>>(x, Ah, Al, N);
    gemm_tc<false><<<ggrid, 256>>>(Ah, Al, Wh1, Wl1, b1, bufB, nullptr, N, F_IN);
    // layer 2
    agg_split_v2<256><<<aggblocks, 256>>>(bufB, Ah, Al, N);
    gemm_tc<false><<<ggrid, 256>>>(Ah, Al, Wh2, Wl2, b2, bufB, nullptr, N, HID);
    // layer 3 (pooling fused into epilogue)
    agg_split_v2<256><<<aggblocks, 256>>>(bufB, Ah, Al, N);
    gemm_tc<true><<<ggrid, 256>>>(Ah, Al, Wh3, Wl3, b3, nullptr, batch, N, HID);

    // head
    head_kernel<<<G, 256>>>(molwt, nrings, fcW1, fcb1, fcW2, fcb2, (float*)d_out);
}